// round 2
// baseline (speedup 1.0000x reference)
#include <cuda_runtime.h>
#include <cuda_bf16.h>
#include <math.h>

// Problem constants
#define B_   2
#define QL_  2048
#define HID_ 2048
#define NH_  32
#define KVH_ 8
#define D_   64

// Scratch (device globals — no allocation allowed)
__device__ float g_Q[(size_t)B_ * NH_  * QL_ * D_];   // [b,h,q,d]
__device__ float g_K[(size_t)B_ * KVH_ * QL_ * D_];
__device__ float g_V[(size_t)B_ * KVH_ * QL_ * D_];
__device__ float g_A[(size_t)B_ * QL_ * HID_];        // attn out, [b*q, h*d] row-major

// ---------------------------------------------------------------------------
// SGEMM: C[M,N] = A[M,K] @ B[K,N].  BM=BN=128, BK=16, 256 thr, 8x8 per thread.
// MODE 0: plain row-major C.
// MODE 1: permuted write: row r=(b*QL+t), col c=(h*64+dd) ->
//         C[((b*H+h)*QL + t)*64 + dd]   (head-major layout for attention)
// ---------------------------------------------------------------------------
template<int MODE>
__global__ void __launch_bounds__(256)
sgemm_kernel(const float* __restrict__ A, const float* __restrict__ B,
             float* __restrict__ C, int M, int N, int K, int H, int QL)
{
    __shared__ __align__(16) float As[16][132];
    __shared__ __align__(16) float Bs[16][132];

    const int tid = threadIdx.x;
    const int tx  = tid & 15;
    const int ty  = tid >> 4;
    const int bx  = blockIdx.x;
    const int by  = blockIdx.y;

    const float* Ab = A + (size_t)by * 128 * K;
    const float* Bb = B + (size_t)bx * 128;

    float acc[8][8];
#pragma unroll
    for (int i = 0; i < 8; i++)
#pragma unroll
        for (int j = 0; j < 8; j++) acc[i][j] = 0.f;

    for (int k0 = 0; k0 < K; k0 += 16) {
        // load A tile (128x16), store transposed As[k][m]
#pragma unroll
        for (int it = 0; it < 2; it++) {
            int f  = tid + it * 256;          // 0..511 float4s
            int ar = f >> 2;
            int a4 = f & 3;
            float4 v = *(const float4*)(Ab + (size_t)ar * K + k0 + a4 * 4);
            As[a4 * 4 + 0][ar] = v.x;
            As[a4 * 4 + 1][ar] = v.y;
            As[a4 * 4 + 2][ar] = v.z;
            As[a4 * 4 + 3][ar] = v.w;
        }
        // load B tile (16x128)
#pragma unroll
        for (int it = 0; it < 2; it++) {
            int f  = tid + it * 256;
            int br = f >> 5;
            int b4 = f & 31;
            *(float4*)&Bs[br][b4 * 4] =
                *(const float4*)(Bb + (size_t)(k0 + br) * N + b4 * 4);
        }
        __syncthreads();

#pragma unroll
        for (int k = 0; k < 16; k++) {
            float4 a0 = *(float4*)&As[k][ty * 4];
            float4 a1 = *(float4*)&As[k][ty * 4 + 64];
            float4 b0 = *(float4*)&Bs[k][tx * 4];
            float4 b1 = *(float4*)&Bs[k][tx * 4 + 64];
            float av[8] = {a0.x, a0.y, a0.z, a0.w, a1.x, a1.y, a1.z, a1.w};
            float bv[8] = {b0.x, b0.y, b0.z, b0.w, b1.x, b1.y, b1.z, b1.w};
#pragma unroll
            for (int i = 0; i < 8; i++)
#pragma unroll
                for (int j = 0; j < 8; j++)
                    acc[i][j] += av[i] * bv[j];
        }
        __syncthreads();
    }

    // epilogue
#pragma unroll
    for (int ih = 0; ih < 2; ih++)
#pragma unroll
        for (int i = 0; i < 4; i++) {
            int gr = by * 128 + ty * 4 + i + ih * 64;
#pragma unroll
            for (int jh = 0; jh < 2; jh++) {
                int gc = bx * 128 + tx * 4 + jh * 64;
                float4 v = make_float4(acc[ih * 4 + i][jh * 4 + 0],
                                       acc[ih * 4 + i][jh * 4 + 1],
                                       acc[ih * 4 + i][jh * 4 + 2],
                                       acc[ih * 4 + i][jh * 4 + 3]);
                if (MODE == 0) {
                    *(float4*)&C[(size_t)gr * N + gc] = v;
                } else {
                    int b = gr / QL, t = gr % QL;
                    int h = gc >> 6, dd = gc & 63;
                    size_t o = (((size_t)b * H + h) * QL + t) * (size_t)64 + dd;
                    *(float4*)&C[o] = v;
                }
            }
        }
}

// ---------------------------------------------------------------------------
// RoPE, in-place on [B, H, Q, 64] buffer. One thread per rotation pair.
//
// IMPORTANT: the harness compiles with --use_fast_math, which turns
// sincosf/powf into MUFU approximations. __sincosf is catastrophically wrong
// for arguments ~2000 rad (no real argument reduction). So: compute freq via
// double pow (matches jnp fp32 pow within 1 ulp), form the angle with the same
// fp32 multiply rounding as the reference, then take DOUBLE-precision sincos
// of that fp32 value. fp64 trig here is cheap (5.2M pairs total).
// ---------------------------------------------------------------------------
__global__ void rope_kernel(float* __restrict__ buf, int Q, int total)
{
    int idx = blockIdx.x * blockDim.x + threadIdx.x;
    if (idx >= total) return;
    int j  = idx & 31;
    int t  = (idx >> 5) % Q;
    int bh = idx / (32 * Q);
    size_t base = ((size_t)bh * Q + t) * 64;

    float freq = (float)(1.0 / pow(10000.0, (double)(2 * j) / 64.0));
    float ang  = (float)t * freq;      // fp32 rounding, same as reference
    double cd, sd;
    sincos((double)ang, &sd, &cd);     // accurate reduction (fp64, fast-math safe)
    float c = (float)cd, s = (float)sd;

    float x1 = buf[base + j];
    float x2 = buf[base + j + 32];
    buf[base + j]      = x1 * c - x2 * s;
    buf[base + j + 32] = x2 * c + x1 * s;
}

// ---------------------------------------------------------------------------
// Causal flash attention with GQA.
// Grid: (Q/128, NH, B). 256 threads. BQ=128, BK=64, D=64.
// Thread (ty,tx): ty=tid/16 owns 8 q-rows, tx=tid%16 owns 4 cols (of S) /
// 4 d-cols (of O).
// SMEM: Qt[64][132] (d-major Q), Kt[64][68] (d-major K), Vs[64][68], Ps[128][68]
// Output written directly in [b*Q, H*64] row-major -> ready for Wo GEMM.
// ---------------------------------------------------------------------------
#define QT_ST 132
#define KV_ST 68
#define ATTN_SMEM_FLOATS (64 * QT_ST + 64 * KV_ST + 64 * KV_ST + 128 * KV_ST)
#define ATTN_SMEM_BYTES  (ATTN_SMEM_FLOATS * 4)

__global__ void __launch_bounds__(256)
attn_kernel(const float* __restrict__ Qb, const float* __restrict__ Kb,
            const float* __restrict__ Vb, float* __restrict__ Ob,
            int Q, int H, int KVH)
{
    extern __shared__ float sm[];
    float* Qt = sm;                        // [64][QT_ST]
    float* Kt = Qt + 64 * QT_ST;           // [64][KV_ST]
    float* Vs = Kt + 64 * KV_ST;           // [64][KV_ST]
    float* Ps = Vs + 64 * KV_ST;           // [128][KV_ST]

    const int tid = threadIdx.x;
    const int tx  = tid & 15;
    const int ty  = tid >> 4;
    const int qt  = blockIdx.x;
    const int h   = blockIdx.y;
    const int b   = blockIdx.z;
    const int kvh = h / (H / KVH);
    const int q0  = qt * 128;

    const float* Qg = Qb + (((size_t)b * H + h) * Q + q0) * 64;
    const float* Kg = Kb + (((size_t)b * KVH + kvh) * Q) * 64;
    const float* Vg = Vb + (((size_t)b * KVH + kvh) * Q) * 64;

    // load Q tile (128x64) -> Qt[d][r]
#pragma unroll
    for (int it = 0; it < 8; it++) {
        int f  = tid + it * 256;   // 0..2047 float4s
        int r  = f >> 4;
        int d4 = f & 15;
        float4 v = *(const float4*)(Qg + (size_t)r * 64 + d4 * 4);
        Qt[(d4 * 4 + 0) * QT_ST + r] = v.x;
        Qt[(d4 * 4 + 1) * QT_ST + r] = v.y;
        Qt[(d4 * 4 + 2) * QT_ST + r] = v.z;
        Qt[(d4 * 4 + 3) * QT_ST + r] = v.w;
    }

    float m[8], l[8], acc[8][4];
#pragma unroll
    for (int i = 0; i < 8; i++) {
        m[i] = -1e30f;
        l[i] = 0.f;
#pragma unroll
        for (int j = 0; j < 4; j++) acc[i][j] = 0.f;
    }

    const int ktiles = (q0 + 128) / 64;   // causal: only tiles up to the diagonal
    const float scale = 0.125f;           // 1/sqrt(64)

    for (int kt = 0; kt < ktiles; kt++) {
        const int k0 = kt * 64;
        __syncthreads();   // previous iteration's readers done (also after Q load)

        // load K tile (64x64) -> Kt[d][c] ; V tile (64x64) -> Vs[c][d]
#pragma unroll
        for (int it = 0; it < 4; it++) {
            int f  = tid + it * 256;   // 0..1023 float4s
            int c  = f >> 4;
            int d4 = f & 15;
            float4 kv = *(const float4*)(Kg + (size_t)(k0 + c) * 64 + d4 * 4);
            Kt[(d4 * 4 + 0) * KV_ST + c] = kv.x;
            Kt[(d4 * 4 + 1) * KV_ST + c] = kv.y;
            Kt[(d4 * 4 + 2) * KV_ST + c] = kv.z;
            Kt[(d4 * 4 + 3) * KV_ST + c] = kv.w;
            float4 vv = *(const float4*)(Vg + (size_t)(k0 + c) * 64 + d4 * 4);
            *(float4*)&Vs[c * KV_ST + d4 * 4] = vv;
        }
        __syncthreads();

        // S = Q K^T  (8 rows x 4 cols per thread)
        float s[8][4];
#pragma unroll
        for (int i = 0; i < 8; i++)
#pragma unroll
            for (int j = 0; j < 4; j++) s[i][j] = 0.f;

#pragma unroll 4
        for (int d = 0; d < 64; d++) {
            float4 q0v = *(float4*)&Qt[d * QT_ST + ty * 8];
            float4 q1v = *(float4*)&Qt[d * QT_ST + ty * 8 + 4];
            float4 kv  = *(float4*)&Kt[d * KV_ST + tx * 4];
            float qv[8] = {q0v.x, q0v.y, q0v.z, q0v.w, q1v.x, q1v.y, q1v.z, q1v.w};
            float kvv[4] = {kv.x, kv.y, kv.z, kv.w};
#pragma unroll
            for (int i = 0; i < 8; i++)
#pragma unroll
                for (int j = 0; j < 4; j++)
                    s[i][j] += qv[i] * kvv[j];
        }

        // scale + causal mask + online softmax
#pragma unroll
        for (int i = 0; i < 8; i++) {
            int qg = q0 + ty * 8 + i;
            float rm = -1e30f;
#pragma unroll
            for (int j = 0; j < 4; j++) {
                int kg = k0 + tx * 4 + j;
                float v = s[i][j] * scale;
                if (kg > qg) v = -1e30f;
                s[i][j] = v;
                rm = fmaxf(rm, v);
            }
#pragma unroll
            for (int off = 8; off; off >>= 1)
                rm = fmaxf(rm, __shfl_xor_sync(0xffffffffu, rm, off));

            float newm = fmaxf(m[i], rm);
            float corr = __expf(m[i] - newm);
            float rsum = 0.f;
#pragma unroll
            for (int j = 0; j < 4; j++) {
                float p = __expf(s[i][j] - newm);
                s[i][j] = p;
                rsum += p;
            }
#pragma unroll
            for (int off = 8; off; off >>= 1)
                rsum += __shfl_xor_sync(0xffffffffu, rsum, off);

            l[i] = l[i] * corr + rsum;
            m[i] = newm;
#pragma unroll
            for (int j = 0; j < 4; j++) acc[i][j] *= corr;

            *(float4*)&Ps[(ty * 8 + i) * KV_ST + tx * 4] =
                make_float4(s[i][0], s[i][1], s[i][2], s[i][3]);
        }
        __syncthreads();

        // O += P @ V
#pragma unroll 4
        for (int k = 0; k < 64; k++) {
            float4 vv = *(float4*)&Vs[k * KV_ST + tx * 4];
#pragma unroll
            for (int i = 0; i < 8; i++) {
                float p = Ps[(ty * 8 + i) * KV_ST + k];
                acc[i][0] += p * vv.x;
                acc[i][1] += p * vv.y;
                acc[i][2] += p * vv.z;
                acc[i][3] += p * vv.w;
            }
        }
    }

    // epilogue: write [b*Q + q, H*64 + h*64 + d] row-major (ready for Wo GEMM)
    const int HIDcols = H * 64;
#pragma unroll
    for (int i = 0; i < 8; i++) {
        float inv = 1.0f / l[i];
        int gr = b * Q + q0 + ty * 8 + i;
        int gc = h * 64 + tx * 4;
        *(float4*)&Ob[(size_t)gr * HIDcols + gc] =
            make_float4(acc[i][0] * inv, acc[i][1] * inv,
                        acc[i][2] * inv, acc[i][3] * inv);
    }
}

// ---------------------------------------------------------------------------
extern "C" void kernel_launch(void* const* d_in, const int* in_sizes, int n_in,
                              void* d_out, int out_size)
{
    const float* X  = (const float*)d_in[0];
    // d_in[1] = attention_mask (always causal; not read)
    const float* Wq = (const float*)d_in[2];
    const float* Wk = (const float*)d_in[3];
    const float* Wv = (const float*)d_in[4];
    const float* Wo = (const float*)d_in[5];
    float* out = (float*)d_out;

    float *qp, *kp, *vp, *ap;
    cudaGetSymbolAddress((void**)&qp, g_Q);
    cudaGetSymbolAddress((void**)&kp, g_K);
    cudaGetSymbolAddress((void**)&vp, g_V);
    cudaGetSymbolAddress((void**)&ap, g_A);

    const int M = B_ * QL_;   // 4096

    // QKV projections with permuted epilogue -> [b,h,q,d]
    sgemm_kernel<1><<<dim3(HID_ / 128, M / 128), 256>>>(X, Wq, qp, M, NH_ * D_,  HID_, NH_,  QL_);
    sgemm_kernel<1><<<dim3((KVH_ * D_) / 128, M / 128), 256>>>(X, Wk, kp, M, KVH_ * D_, HID_, KVH_, QL_);
    sgemm_kernel<1><<<dim3((KVH_ * D_) / 128, M / 128), 256>>>(X, Wv, vp, M, KVH_ * D_, HID_, KVH_, QL_);

    // RoPE on Q and K
    {
        int totq = B_ * NH_  * QL_ * 32;
        int totk = B_ * KVH_ * QL_ * 32;
        rope_kernel<<<(totq + 255) / 256, 256>>>(qp, QL_, totq);
        rope_kernel<<<(totk + 255) / 256, 256>>>(kp, QL_, totk);
    }

    // Attention
    cudaFuncSetAttribute(attn_kernel,
                         cudaFuncAttributeMaxDynamicSharedMemorySize,
                         ATTN_SMEM_BYTES);
    attn_kernel<<<dim3(QL_ / 128, NH_, B_), 256, ATTN_SMEM_BYTES>>>(
        qp, kp, vp, ap, QL_, NH_, KVH_);

    // Output projection
    sgemm_kernel<0><<<dim3(HID_ / 128, M / 128), 256>>>(ap, Wo, out, M, HID_, HID_, 0, 0);
}

// round 3
// speedup vs baseline: 1.4367x; 1.4367x over previous
#include <cuda_runtime.h>
#include <cuda_bf16.h>
#include <math.h>

// Problem constants
#define B_   2
#define QL_  2048
#define HID_ 2048
#define NH_  32
#define KVH_ 8
#define D_   64

// Scratch (device globals — no allocation allowed)
__device__ float g_Q[(size_t)B_ * NH_  * QL_ * D_];   // [b,h,q,d]
__device__ float g_K[(size_t)B_ * KVH_ * QL_ * D_];
__device__ float g_V[(size_t)B_ * KVH_ * QL_ * D_];
__device__ float g_A[(size_t)B_ * QL_ * HID_];        // attn out, [b*q, h*d] row-major
__device__ float g_cos[QL_ * 32];                     // RoPE tables [t][j]
__device__ float g_sin[QL_ * 32];

// ---------------------------------------------------------------------------
// SGEMM: C[M,N] = A[M,K] @ B[K,N].  BM=BN=128, BK=16, 256 thr, 8x8 per thread.
// Register-prefetch double buffering: tile k+1 GMEM loads issue before the
// FFMA loop of tile k.
// MODE 0: plain row-major C.
// MODE 1: permuted write: row r=(b*QL+t), col c=(h*64+dd) ->
//         C[((b*H+h)*QL + t)*64 + dd]   (head-major layout for attention)
// ---------------------------------------------------------------------------
template<int MODE>
__global__ void __launch_bounds__(256)
sgemm_kernel(const float* __restrict__ A, const float* __restrict__ B,
             float* __restrict__ C, int M, int N, int K, int H, int QL)
{
    __shared__ __align__(16) float As[16][132];
    __shared__ __align__(16) float Bs[16][132];

    const int tid = threadIdx.x;
    const int tx  = tid & 15;
    const int ty  = tid >> 4;
    const int bx  = blockIdx.x;
    const int by  = blockIdx.y;

    const float* Ab = A + (size_t)by * 128 * K;
    const float* Bb = B + (size_t)bx * 128;

    // per-thread load coordinates (invariant across k tiles)
    const int ar0 = (tid)       >> 2, a40 = (tid)       & 3;
    const int ar1 = (tid + 256) >> 2, a41 = (tid + 256) & 3;
    const int br0 = (tid)       >> 5, b40 = (tid)       & 31;
    const int br1 = (tid + 256) >> 5, b41 = (tid + 256) & 31;

    float acc[8][8];
#pragma unroll
    for (int i = 0; i < 8; i++)
#pragma unroll
        for (int j = 0; j < 8; j++) acc[i][j] = 0.f;

    // prefetch tile 0 into registers
    float4 pA0 = *(const float4*)(Ab + (size_t)ar0 * K + a40 * 4);
    float4 pA1 = *(const float4*)(Ab + (size_t)ar1 * K + a41 * 4);
    float4 pB0 = *(const float4*)(Bb + (size_t)br0 * N + b40 * 4);
    float4 pB1 = *(const float4*)(Bb + (size_t)br1 * N + b41 * 4);

    for (int k0 = 0; k0 < K; k0 += 16) {
        // store prefetched tile to SMEM (A transposed)
        As[a40 * 4 + 0][ar0] = pA0.x;
        As[a40 * 4 + 1][ar0] = pA0.y;
        As[a40 * 4 + 2][ar0] = pA0.z;
        As[a40 * 4 + 3][ar0] = pA0.w;
        As[a41 * 4 + 0][ar1] = pA1.x;
        As[a41 * 4 + 1][ar1] = pA1.y;
        As[a41 * 4 + 2][ar1] = pA1.z;
        As[a41 * 4 + 3][ar1] = pA1.w;
        *(float4*)&Bs[br0][b40 * 4] = pB0;
        *(float4*)&Bs[br1][b41 * 4] = pB1;
        __syncthreads();

        // prefetch next tile (overlaps with FFMA loop below)
        if (k0 + 16 < K) {
            pA0 = *(const float4*)(Ab + (size_t)ar0 * K + k0 + 16 + a40 * 4);
            pA1 = *(const float4*)(Ab + (size_t)ar1 * K + k0 + 16 + a41 * 4);
            pB0 = *(const float4*)(Bb + (size_t)(k0 + 16 + br0) * N + b40 * 4);
            pB1 = *(const float4*)(Bb + (size_t)(k0 + 16 + br1) * N + b41 * 4);
        }

#pragma unroll
        for (int k = 0; k < 16; k++) {
            float4 a0 = *(float4*)&As[k][ty * 4];
            float4 a1 = *(float4*)&As[k][ty * 4 + 64];
            float4 b0 = *(float4*)&Bs[k][tx * 4];
            float4 b1 = *(float4*)&Bs[k][tx * 4 + 64];
            float av[8] = {a0.x, a0.y, a0.z, a0.w, a1.x, a1.y, a1.z, a1.w};
            float bv[8] = {b0.x, b0.y, b0.z, b0.w, b1.x, b1.y, b1.z, b1.w};
#pragma unroll
            for (int i = 0; i < 8; i++)
#pragma unroll
                for (int j = 0; j < 8; j++)
                    acc[i][j] += av[i] * bv[j];
        }
        __syncthreads();
    }

    // epilogue
#pragma unroll
    for (int ih = 0; ih < 2; ih++)
#pragma unroll
        for (int i = 0; i < 4; i++) {
            int gr = by * 128 + ty * 4 + i + ih * 64;
#pragma unroll
            for (int jh = 0; jh < 2; jh++) {
                int gc = bx * 128 + tx * 4 + jh * 64;
                float4 v = make_float4(acc[ih * 4 + i][jh * 4 + 0],
                                       acc[ih * 4 + i][jh * 4 + 1],
                                       acc[ih * 4 + i][jh * 4 + 2],
                                       acc[ih * 4 + i][jh * 4 + 3]);
                if (MODE == 0) {
                    *(float4*)&C[(size_t)gr * N + gc] = v;
                } else {
                    int b = gr / QL, t = gr % QL;
                    int h = gc >> 6, dd = gc & 63;
                    size_t o = (((size_t)b * H + h) * QL + t) * (size_t)64 + dd;
                    *(float4*)&C[o] = v;
                }
            }
        }
}

// ---------------------------------------------------------------------------
// RoPE cos/sin table: one entry per (t, j), computed ONCE in fp64.
// --use_fast_math breaks sincosf for args ~2000 rad; fp64 sincos of the
// reference's fp32 angle matches jnp to ~1e-7. Only 65536 entries -> ~10us.
// ---------------------------------------------------------------------------
__global__ void rope_table_kernel(float* __restrict__ ct, float* __restrict__ st,
                                  int Q)
{
    int idx = blockIdx.x * blockDim.x + threadIdx.x;
    if (idx >= Q * 32) return;
    int j = idx & 31;
    int t = idx >> 5;
    float freq = (float)(1.0 / pow(10000.0, (double)(2 * j) / 64.0));
    float ang  = (float)t * freq;      // fp32 rounding, same as reference
    double cd, sd;
    sincos((double)ang, &sd, &cd);
    ct[idx] = (float)cd;
    st[idx] = (float)sd;
}

// RoPE apply, in-place on [B, H, Q, 64]: memory-bound table lookup.
__global__ void rope_apply_kernel(float* __restrict__ buf,
                                  const float* __restrict__ ct,
                                  const float* __restrict__ st,
                                  int Q, int total)
{
    int idx = blockIdx.x * blockDim.x + threadIdx.x;
    if (idx >= total) return;
    int j  = idx & 31;
    int t  = (idx >> 5) % Q;
    int bh = idx / (32 * Q);
    size_t base = ((size_t)bh * Q + t) * 64;

    float c = ct[(t << 5) + j];
    float s = st[(t << 5) + j];

    float x1 = buf[base + j];
    float x2 = buf[base + j + 32];
    buf[base + j]      = x1 * c - x2 * s;
    buf[base + j + 32] = x2 * c + x1 * s;
}

// ---------------------------------------------------------------------------
// Causal flash attention with GQA.
// Grid: (Q/128, NH, B). 256 threads. BQ=128, BK=64, D=64.
// ---------------------------------------------------------------------------
#define QT_ST 132
#define KV_ST 68
#define ATTN_SMEM_FLOATS (64 * QT_ST + 64 * KV_ST + 64 * KV_ST + 128 * KV_ST)
#define ATTN_SMEM_BYTES  (ATTN_SMEM_FLOATS * 4)

__global__ void __launch_bounds__(256)
attn_kernel(const float* __restrict__ Qb, const float* __restrict__ Kb,
            const float* __restrict__ Vb, float* __restrict__ Ob,
            int Q, int H, int KVH)
{
    extern __shared__ float sm[];
    float* Qt = sm;                        // [64][QT_ST]
    float* Kt = Qt + 64 * QT_ST;           // [64][KV_ST]
    float* Vs = Kt + 64 * KV_ST;           // [64][KV_ST]
    float* Ps = Vs + 64 * KV_ST;           // [128][KV_ST]

    const int tid = threadIdx.x;
    const int tx  = tid & 15;
    const int ty  = tid >> 4;
    const int qt  = blockIdx.x;
    const int h   = blockIdx.y;
    const int b   = blockIdx.z;
    const int kvh = h / (H / KVH);
    const int q0  = qt * 128;

    const float* Qg = Qb + (((size_t)b * H + h) * Q + q0) * 64;
    const float* Kg = Kb + (((size_t)b * KVH + kvh) * Q) * 64;
    const float* Vg = Vb + (((size_t)b * KVH + kvh) * Q) * 64;

    // load Q tile (128x64) -> Qt[d][r]
#pragma unroll
    for (int it = 0; it < 8; it++) {
        int f  = tid + it * 256;   // 0..2047 float4s
        int r  = f >> 4;
        int d4 = f & 15;
        float4 v = *(const float4*)(Qg + (size_t)r * 64 + d4 * 4);
        Qt[(d4 * 4 + 0) * QT_ST + r] = v.x;
        Qt[(d4 * 4 + 1) * QT_ST + r] = v.y;
        Qt[(d4 * 4 + 2) * QT_ST + r] = v.z;
        Qt[(d4 * 4 + 3) * QT_ST + r] = v.w;
    }

    float m[8], l[8], acc[8][4];
#pragma unroll
    for (int i = 0; i < 8; i++) {
        m[i] = -1e30f;
        l[i] = 0.f;
#pragma unroll
        for (int j = 0; j < 4; j++) acc[i][j] = 0.f;
    }

    const int ktiles = (q0 + 128) / 64;   // causal: only tiles up to the diagonal
    const float scale = 0.125f;           // 1/sqrt(64)

    for (int kt = 0; kt < ktiles; kt++) {
        const int k0 = kt * 64;
        __syncthreads();   // previous iteration's readers done (also after Q load)

        // load K tile (64x64) -> Kt[d][c] ; V tile (64x64) -> Vs[c][d]
#pragma unroll
        for (int it = 0; it < 4; it++) {
            int f  = tid + it * 256;   // 0..1023 float4s
            int c  = f >> 4;
            int d4 = f & 15;
            float4 kv = *(const float4*)(Kg + (size_t)(k0 + c) * 64 + d4 * 4);
            Kt[(d4 * 4 + 0) * KV_ST + c] = kv.x;
            Kt[(d4 * 4 + 1) * KV_ST + c] = kv.y;
            Kt[(d4 * 4 + 2) * KV_ST + c] = kv.z;
            Kt[(d4 * 4 + 3) * KV_ST + c] = kv.w;
            float4 vv = *(const float4*)(Vg + (size_t)(k0 + c) * 64 + d4 * 4);
            *(float4*)&Vs[c * KV_ST + d4 * 4] = vv;
        }
        __syncthreads();

        // S = Q K^T  (8 rows x 4 cols per thread)
        float s[8][4];
#pragma unroll
        for (int i = 0; i < 8; i++)
#pragma unroll
            for (int j = 0; j < 4; j++) s[i][j] = 0.f;

#pragma unroll 4
        for (int d = 0; d < 64; d++) {
            float4 q0v = *(float4*)&Qt[d * QT_ST + ty * 8];
            float4 q1v = *(float4*)&Qt[d * QT_ST + ty * 8 + 4];
            float4 kv  = *(float4*)&Kt[d * KV_ST + tx * 4];
            float qv[8] = {q0v.x, q0v.y, q0v.z, q0v.w, q1v.x, q1v.y, q1v.z, q1v.w};
            float kvv[4] = {kv.x, kv.y, kv.z, kv.w};
#pragma unroll
            for (int i = 0; i < 8; i++)
#pragma unroll
                for (int j = 0; j < 4; j++)
                    s[i][j] += qv[i] * kvv[j];
        }

        // scale + causal mask + online softmax
#pragma unroll
        for (int i = 0; i < 8; i++) {
            int qg = q0 + ty * 8 + i;
            float rm = -1e30f;
#pragma unroll
            for (int j = 0; j < 4; j++) {
                int kg = k0 + tx * 4 + j;
                float v = s[i][j] * scale;
                if (kg > qg) v = -1e30f;
                s[i][j] = v;
                rm = fmaxf(rm, v);
            }
#pragma unroll
            for (int off = 8; off; off >>= 1)
                rm = fmaxf(rm, __shfl_xor_sync(0xffffffffu, rm, off));

            float newm = fmaxf(m[i], rm);
            float corr = __expf(m[i] - newm);
            float rsum = 0.f;
#pragma unroll
            for (int j = 0; j < 4; j++) {
                float p = __expf(s[i][j] - newm);
                s[i][j] = p;
                rsum += p;
            }
#pragma unroll
            for (int off = 8; off; off >>= 1)
                rsum += __shfl_xor_sync(0xffffffffu, rsum, off);

            l[i] = l[i] * corr + rsum;
            m[i] = newm;
#pragma unroll
            for (int j = 0; j < 4; j++) acc[i][j] *= corr;

            *(float4*)&Ps[(ty * 8 + i) * KV_ST + tx * 4] =
                make_float4(s[i][0], s[i][1], s[i][2], s[i][3]);
        }
        __syncthreads();

        // O += P @ V
#pragma unroll 4
        for (int k = 0; k < 64; k++) {
            float4 vv = *(float4*)&Vs[k * KV_ST + tx * 4];
#pragma unroll
            for (int i = 0; i < 8; i++) {
                float p = Ps[(ty * 8 + i) * KV_ST + k];
                acc[i][0] += p * vv.x;
                acc[i][1] += p * vv.y;
                acc[i][2] += p * vv.z;
                acc[i][3] += p * vv.w;
            }
        }
    }

    // epilogue: write [b*Q + q, H*64 + h*64 + d] row-major (ready for Wo GEMM)
    const int HIDcols = H * 64;
#pragma unroll
    for (int i = 0; i < 8; i++) {
        float inv = 1.0f / l[i];
        int gr = b * Q + q0 + ty * 8 + i;
        int gc = h * 64 + tx * 4;
        *(float4*)&Ob[(size_t)gr * HIDcols + gc] =
            make_float4(acc[i][0] * inv, acc[i][1] * inv,
                        acc[i][2] * inv, acc[i][3] * inv);
    }
}

// ---------------------------------------------------------------------------
extern "C" void kernel_launch(void* const* d_in, const int* in_sizes, int n_in,
                              void* d_out, int out_size)
{
    const float* X  = (const float*)d_in[0];
    // d_in[1] = attention_mask (always causal; not read)
    const float* Wq = (const float*)d_in[2];
    const float* Wk = (const float*)d_in[3];
    const float* Wv = (const float*)d_in[4];
    const float* Wo = (const float*)d_in[5];
    float* out = (float*)d_out;

    float *qp, *kp, *vp, *ap, *cp, *sp;
    cudaGetSymbolAddress((void**)&qp, g_Q);
    cudaGetSymbolAddress((void**)&kp, g_K);
    cudaGetSymbolAddress((void**)&vp, g_V);
    cudaGetSymbolAddress((void**)&ap, g_A);
    cudaGetSymbolAddress((void**)&cp, g_cos);
    cudaGetSymbolAddress((void**)&sp, g_sin);

    const int M = B_ * QL_;   // 4096

    // RoPE table (independent of GEMMs — launch first)
    rope_table_kernel<<<(QL_ * 32 + 255) / 256, 256>>>(cp, sp, QL_);

    // QKV projections with permuted epilogue -> [b,h,q,d]
    sgemm_kernel<1><<<dim3(HID_ / 128, M / 128), 256>>>(X, Wq, qp, M, NH_ * D_,  HID_, NH_,  QL_);
    sgemm_kernel<1><<<dim3((KVH_ * D_) / 128, M / 128), 256>>>(X, Wk, kp, M, KVH_ * D_, HID_, KVH_, QL_);
    sgemm_kernel<1><<<dim3((KVH_ * D_) / 128, M / 128), 256>>>(X, Wv, vp, M, KVH_ * D_, HID_, KVH_, QL_);

    // RoPE on Q and K (table lookup, memory-bound)
    {
        int totq = B_ * NH_  * QL_ * 32;
        int totk = B_ * KVH_ * QL_ * 32;
        rope_apply_kernel<<<(totq + 255) / 256, 256>>>(qp, cp, sp, QL_, totq);
        rope_apply_kernel<<<(totk + 255) / 256, 256>>>(kp, cp, sp, QL_, totk);
    }

    // Attention
    cudaFuncSetAttribute(attn_kernel,
                         cudaFuncAttributeMaxDynamicSharedMemorySize,
                         ATTN_SMEM_BYTES);
    attn_kernel<<<dim3(QL_ / 128, NH_, B_), 256, ATTN_SMEM_BYTES>>>(
        qp, kp, vp, ap, QL_, NH_, KVH_);

    // Output projection
    sgemm_kernel<0><<<dim3(HID_ / 128, M / 128), 256>>>(ap, Wo, out, M, HID_, HID_, 0, 0);
}